// round 2
// baseline (speedup 1.0000x reference)
#include <cuda_runtime.h>

#define B_   2
#define SQ_  2048
#define SK_  2048
#define D_   1024
#define H_   16
#define HD_  64

// Scratch (allocation-free rule: __device__ globals)
__device__ float g_q[B_*H_*SQ_*HD_];     // [B,H,SQ,HD]
__device__ float g_k[B_*H_*SK_*HD_];     // [B,H,SK,HD]
__device__ float g_v[B_*H_*SK_*HD_];     // [B,H,SK,HD]
__device__ float g_attn[B_*SQ_*D_];      // [B,SQ,D] (heads concatenated)

// ----------------------------------------------------------------------------
// SGEMM: C[M,N] = A[M,K] @ B'[K,N] + bias[N]
// BMODE 0: Bm row-major [K,N].
// BMODE 1: Bm is per-head weight [H, K, 64]; logical col n -> (h=n>>6, e=n&63),
//          element B'[k][n] = Bm[(h*K + k)*64 + e].
// OMODE 0: C row-major [M,N].
// OMODE 1: C as [B,H,S,64]: row=b*S+s, col=h*64+e -> ((b*H+h)*S+s)*64+e.
// Tile: 128x128x8, 256 threads, 8x8 per thread.
// ----------------------------------------------------------------------------
template<int BMODE, int OMODE>
__global__ __launch_bounds__(256) void sgemm(
    const float* __restrict__ A, const float* __restrict__ Bm,
    const float* __restrict__ bias, float* __restrict__ C,
    int M, int N, int K, int S)
{
    const int BK = 8;
    __shared__ float As[BK][128];   // transposed A tile: As[k][m]
    __shared__ float Bs[BK][128];   // Bs[k][n]

    int tid = threadIdx.x;
    int tx = tid & 15, ty = tid >> 4;              // 16x16 thread grid
    int row0 = blockIdx.y * 128, col0 = blockIdx.x * 128;

    int arow = tid >> 1, acol = (tid & 1) * 4;     // A tile: 128 rows x 8 cols
    int brow = tid >> 5, bcol = (tid & 31) * 4;    // B tile: 8 rows x 128 cols

    float acc[8][8];
#pragma unroll
    for (int i = 0; i < 8; i++)
#pragma unroll
        for (int j = 0; j < 8; j++) acc[i][j] = 0.f;

    const float* Aptr = A + (long long)(row0 + arow) * K + acol;

    for (int k0 = 0; k0 < K; k0 += BK) {
        float4 av = *(const float4*)(Aptr + k0);
        As[acol + 0][arow] = av.x;
        As[acol + 1][arow] = av.y;
        As[acol + 2][arow] = av.z;
        As[acol + 3][arow] = av.w;

        float4 bv;
        if (BMODE == 0) {
            bv = *(const float4*)&Bm[(long long)(k0 + brow) * N + col0 + bcol];
        } else {
            int n = col0 + bcol;
            int h = n >> 6, e = n & 63;
            bv = *(const float4*)&Bm[((long long)h * K + (k0 + brow)) * HD_ + e];
        }
        *(float4*)&Bs[brow][bcol] = bv;

        __syncthreads();

#pragma unroll
        for (int kk = 0; kk < BK; kk++) {
            float ar[8], br[8];
            *(float4*)&ar[0] = *(const float4*)&As[kk][ty * 8];
            *(float4*)&ar[4] = *(const float4*)&As[kk][ty * 8 + 4];
            *(float4*)&br[0] = *(const float4*)&Bs[kk][tx * 8];
            *(float4*)&br[4] = *(const float4*)&Bs[kk][tx * 8 + 4];
#pragma unroll
            for (int i = 0; i < 8; i++)
#pragma unroll
                for (int j = 0; j < 8; j++)
                    acc[i][j] += ar[i] * br[j];
        }
        __syncthreads();
    }

    // Epilogue: bias + store (float4)
#pragma unroll
    for (int i = 0; i < 8; i++) {
        int row = row0 + ty * 8 + i;
#pragma unroll
        for (int j4 = 0; j4 < 8; j4 += 4) {
            int col = col0 + tx * 8 + j4;
            float4 o;
            o.x = acc[i][j4 + 0] + bias[col + 0];
            o.y = acc[i][j4 + 1] + bias[col + 1];
            o.z = acc[i][j4 + 2] + bias[col + 2];
            o.w = acc[i][j4 + 3] + bias[col + 3];
            long long idx;
            if (OMODE == 0) {
                idx = (long long)row * N + col;
            } else {
                int b = row / S, s = row - b * S;
                int h = col >> 6, e = col & 63;
                idx = (((long long)(b * H_ + h) * S) + s) * HD_ + e;
            }
            *(float4*)&C[idx] = o;
        }
    }
}

// ----------------------------------------------------------------------------
// Flash attention (fp32): per block = 64 query rows of one (b,h).
// Online softmax; O accumulator in registers (4x4 per thread, 256 threads).
// Score scale folded into Q load. K stored transposed in smem so the inner
// loops read conflict-free float4s.
// smem: Qs[64][68] + Kst[64][68] + Vs[64][68] + Ps[64][68] = 69632 B (dynamic)
// ----------------------------------------------------------------------------
__global__ __launch_bounds__(256) void flash_attn(
    const float* __restrict__ Q, const float* __restrict__ Kg,
    const float* __restrict__ Vg, float* __restrict__ Og)
{
    extern __shared__ float sm[];
    float (*Qs)[68]  = (float(*)[68])(sm);             // [q_row][d]
    float (*Kst)[68] = (float(*)[68])(sm + 64 * 68);   // [d][key]   (transposed)
    float (*Vs)[68]  = (float(*)[68])(sm + 2 * 64 * 68); // [key][d]
    float (*Ps)[68]  = (float(*)[68])(sm + 3 * 64 * 68); // [q_row][key]

    int tid = threadIdx.x;
    int tx = tid & 15, ty = tid >> 4;
    int bh = blockIdx.y;               // b*H + h
    int qbase = blockIdx.x * 64;

    const float* Qp = Q + ((long long)bh * SQ_ + qbase) * HD_;
    const float* Kp = Kg + (long long)bh * SK_ * HD_;
    const float* Vp = Vg + (long long)bh * SK_ * HD_;

    // Load Q tile, pre-scaled by 1/sqrt(HD)
    for (int i = tid; i < 64 * 64; i += 256) {
        int r = i >> 6, d = i & 63;
        Qs[r][d] = Qp[(long long)r * HD_ + d] * 0.125f;
    }

    float m_i[4], l_i[4], acc[4][4];
#pragma unroll
    for (int i = 0; i < 4; i++) {
        m_i[i] = -1e30f; l_i[i] = 0.f;
#pragma unroll
        for (int j = 0; j < 4; j++) acc[i][j] = 0.f;
    }

    for (int kt = 0; kt < SK_; kt += 64) {
        __syncthreads();   // protect Kst/Vs/Ps from previous iteration's readers
        for (int i = tid; i < 64 * 64; i += 256) {
            int r = i >> 6, d = i & 63;
            Kst[d][r] = Kp[(long long)(kt + r) * HD_ + d];
            Vs[r][d]  = Vp[(long long)(kt + r) * HD_ + d];
        }
        __syncthreads();

        // S = Q @ K^T (scale already in Q)
        float s[4][4];
#pragma unroll
        for (int i = 0; i < 4; i++)
#pragma unroll
            for (int j = 0; j < 4; j++) s[i][j] = 0.f;

#pragma unroll 8
        for (int d = 0; d < 64; d++) {
            float4 kv = *(const float4*)&Kst[d][tx * 4];
#pragma unroll
            for (int i = 0; i < 4; i++) {
                float qv = Qs[ty * 4 + i][d];
                s[i][0] += qv * kv.x;
                s[i][1] += qv * kv.y;
                s[i][2] += qv * kv.z;
                s[i][3] += qv * kv.w;
            }
        }

        // Online softmax per row; rows of one q-row live in one 16-lane group.
#pragma unroll
        for (int i = 0; i < 4; i++) {
            float mx = fmaxf(fmaxf(s[i][0], s[i][1]), fmaxf(s[i][2], s[i][3]));
#pragma unroll
            for (int off = 8; off >= 1; off >>= 1)
                mx = fmaxf(mx, __shfl_xor_sync(0xffffffffu, mx, off));
            float mnew = fmaxf(m_i[i], mx);
            float corr = __expf(m_i[i] - mnew);
            m_i[i] = mnew;
            float rs = 0.f;
#pragma unroll
            for (int j = 0; j < 4; j++) {
                s[i][j] = __expf(s[i][j] - mnew);
                rs += s[i][j];
            }
#pragma unroll
            for (int off = 8; off >= 1; off >>= 1)
                rs += __shfl_xor_sync(0xffffffffu, rs, off);
            l_i[i] = l_i[i] * corr + rs;
#pragma unroll
            for (int j = 0; j < 4; j++) acc[i][j] *= corr;
            *(float4*)&Ps[ty * 4 + i][tx * 4] =
                make_float4(s[i][0], s[i][1], s[i][2], s[i][3]);
        }
        __syncthreads();

        // O += P @ V
#pragma unroll 8
        for (int k2 = 0; k2 < 64; k2++) {
            float4 vv = *(const float4*)&Vs[k2][tx * 4];
#pragma unroll
            for (int i = 0; i < 4; i++) {
                float pv = Ps[ty * 4 + i][k2];
                acc[i][0] += pv * vv.x;
                acc[i][1] += pv * vv.y;
                acc[i][2] += pv * vv.z;
                acc[i][3] += pv * vv.w;
            }
        }
    }

    // Normalize and store to [B,SQ,D] with heads concatenated.
    int b = bh >> 4, h = bh & 15;   // H_ == 16
#pragma unroll
    for (int i = 0; i < 4; i++) {
        float inv = 1.f / l_i[i];
        int srow = qbase + ty * 4 + i;
        float4 o = make_float4(acc[i][0] * inv, acc[i][1] * inv,
                               acc[i][2] * inv, acc[i][3] * inv);
        *(float4*)&Og[((long long)b * SQ_ + srow) * D_ + h * HD_ + tx * 4] = o;
    }
}

// ----------------------------------------------------------------------------
extern "C" void kernel_launch(void* const* d_in, const int* in_sizes, int n_in,
                              void* d_out, int out_size)
{
    const float* x   = (const float*)d_in[0];
    const float* enc = (const float*)d_in[1];
    const float* Wq  = (const float*)d_in[2];
    const float* bq  = (const float*)d_in[3];
    const float* Wk  = (const float*)d_in[4];
    const float* bk  = (const float*)d_in[5];
    const float* Wv  = (const float*)d_in[6];
    const float* bv  = (const float*)d_in[7];
    const float* Wo  = (const float*)d_in[8];
    const float* bo  = (const float*)d_in[9];
    float* out = (float*)d_out;

    float *q, *k, *v, *attn;
    cudaGetSymbolAddress((void**)&q,    g_q);
    cudaGetSymbolAddress((void**)&k,    g_k);
    cudaGetSymbolAddress((void**)&v,    g_v);
    cudaGetSymbolAddress((void**)&attn, g_attn);

    dim3 gq(D_ / 128, (B_ * SQ_) / 128);   // N=1024, M=4096 -> 8 x 32 blocks

    // QKV projections straight into [B,H,S,HD]
    sgemm<1, 1><<<gq, 256>>>(x,   Wq, bq, q, B_ * SQ_, D_, D_, SQ_);
    sgemm<1, 1><<<gq, 256>>>(enc, Wk, bk, k, B_ * SK_, D_, D_, SK_);
    sgemm<1, 1><<<gq, 256>>>(enc, Wv, bv, v, B_ * SK_, D_, D_, SK_);

    // Flash attention -> [B,SQ,D]
    int smem = 4 * 64 * 68 * (int)sizeof(float);   // 69632 B
    cudaFuncSetAttribute(flash_attn,
                         cudaFuncAttributeMaxDynamicSharedMemorySize, smem);
    flash_attn<<<dim3(SQ_ / 64, B_ * H_), 256, smem>>>(q, k, v, attn);

    // Final projection + bias -> d_out
    sgemm<0, 0><<<gq, 256>>>(attn, Wo, bo, out, B_ * SQ_, D_, D_, SQ_);
}